// round 13
// baseline (speedup 1.0000x reference)
#include <cuda_runtime.h>
#include <cuda_fp16.h>
#include <math_constants.h>
#include <stdint.h>

// Problem dims
#define B_   4
#define T_   1024
#define H_   12
#define C_   4096
#define DK_  64
#define DV_  64
#define N_   (B_*T_)      // 4096
#define DIM_ (H_*DK_)     // 768

// GEMM config: single-phase fp16 (K=64), certification window handles error.
#define TM   128          // rows per CTA
#define TCB  128          // codes per barrier span (2 x 64-code subtiles)
#define NCT  (C_/TCB)     // 32
#define SA   144          // smem row stride bytes (128 data + 16 pad)
#define B_TILE_BYTES (TCB*SA)     // 18432
#define W_SEL 5e-4f       // ambiguity window (~20 sigma of fp16-GEMM error)

// smem offsets
#define OFF_A   0                 // 128 * 144 = 18432
#define OFF_B   18432             // 2 buffers of 18432
#define OFF_E2  55296             // float e2s[2][128]
#define SMEM_SZ 56320

// Device scratch
__device__ __align__(1024) __half g_Bh[(size_t)H_*C_*DK_];
__device__ float g_e2[H_*C_];
__device__ int   g_idx[H_*N_];
__device__ int   g_listB[H_*N_];
__device__ int   g_cntB;

// ---------------- helpers ----------------
__device__ __forceinline__ uint32_t smem_u32(const void* p) {
    uint32_t a;
    asm("{ .reg .u64 t; cvta.to.shared.u64 t, %1; cvt.u32.u64 %0, t; }" : "=r"(a) : "l"(p));
    return a;
}
__device__ __forceinline__ void cpa16(uint32_t dst, const void* src) {
    asm volatile("cp.async.cg.shared.global [%0], [%1], 16;" :: "r"(dst), "l"(src));
}
__device__ __forceinline__ void cpa_commit() { asm volatile("cp.async.commit_group;" ::: "memory"); }
__device__ __forceinline__ void cpa_wait0()  { asm volatile("cp.async.wait_group 0;" ::: "memory"); }

__device__ __forceinline__ void ldsm4(uint32_t* r, uint32_t addr) {
    asm volatile("ldmatrix.sync.aligned.m8n8.x4.shared.b16 {%0,%1,%2,%3}, [%4];"
                 : "=r"(r[0]), "=r"(r[1]), "=r"(r[2]), "=r"(r[3]) : "r"(addr));
}
__device__ __forceinline__ void mma16816(float* d, const uint32_t* a, const uint32_t* b) {
    asm volatile("mma.sync.aligned.m16n8k16.row.col.f32.f16.f16.f32 "
                 "{%0,%1,%2,%3}, {%4,%5,%6,%7}, {%8,%9}, {%0,%1,%2,%3};"
                 : "+f"(d[0]), "+f"(d[1]), "+f"(d[2]), "+f"(d[3])
                 : "r"(a[0]), "r"(a[1]), "r"(a[2]), "r"(a[3]), "r"(b[0]), "r"(b[1]));
}

__device__ __forceinline__ void merge3(float& m1, int& i1, float& m2, int& i2, float& m3,
                                       float bm1, int bi1, float bm2, int bi2, float bm3) {
    if (bm1 < m1 || (bm1 == m1 && bi1 < i1)) {
        float t; int ti;
        t = m1; m1 = bm1; bm1 = t;  ti = i1; i1 = bi1; bi1 = ti;
        t = m2; m2 = bm2; bm2 = t;  ti = i2; i2 = bi2; bi2 = ti;
        t = m3; m3 = bm3; bm3 = t;
    }
    if (bm1 < m2 || (bm1 == m2 && bi1 < i2)) {
        m3 = fminf(m2, bm2);
        m2 = bm1; i2 = bi1;
    } else {
        m3 = fminf(m3, bm1);
    }
}

__device__ __forceinline__ void ins3(float s, int c, float& m1, int& i1,
                                     float& m2, int& i2, float& m3) {
    if (s < m1)      { m3 = m2; m2 = m1; i2 = i1; m1 = s; i1 = c; }
    else if (s < m2) { m3 = m2; m2 = s; i2 = c; }
    else if (s < m3) { m3 = s; }
}

// ---------------------------------------------------------------------------
// Fused prep: e2 (exact sequential order) + B fp16 convert
// ---------------------------------------------------------------------------
__global__ void prep_be2_kernel(const float* __restrict__ ke) {
    __shared__ float kt[64 * 65];
    const int tid = threadIdx.x;
    const int row0 = blockIdx.x * 64;
    if (blockIdx.x == 0 && tid == 0) g_cntB = 0;

#pragma unroll 4
    for (int m = tid; m < 64 * 16; m += 256) {
        int r = m >> 4, c4 = m & 15;
        float4 v = *(const float4*)(ke + (size_t)(row0 + r) * DK_ + c4 * 4);
        kt[r * 65 + c4 * 4 + 0] = v.x;
        kt[r * 65 + c4 * 4 + 1] = v.y;
        kt[r * 65 + c4 * 4 + 2] = v.z;
        kt[r * 65 + c4 * 4 + 3] = v.w;
    }
    __syncthreads();

    if (tid < 64) {
        float s = 0.f;
#pragma unroll
        for (int d = 0; d < DK_; d++) {
            float v = kt[tid * 65 + d];
            s = __fmaf_rn(v, v, s);
        }
        g_e2[row0 + tid] = s;
    }

#pragma unroll 4
    for (int m = tid; m < 64 * 32; m += 256) {
        int r = m >> 5, dp = m & 31;
        __half2 hv = __floats2half2_rn(kt[r * 65 + dp * 2], kt[r * 65 + dp * 2 + 1]);
        *(__half2*)(g_Bh + (size_t)(row0 + r) * DK_ + dp * 2) = hv;
    }
}

// ---------------------------------------------------------------------------
// Main: fp16 HMMA GEMM (K=64) + top-3 argmin, barrier per 128 codes,
// round-11 epilogue (acc consumed in scan order; registers retire early)
// grid = (32, 12); block = 128 (4 warps, each 32 rows x 64 cols per subtile)
// ---------------------------------------------------------------------------
__global__ __launch_bounds__(128, 3)
void hmma_argmin_kernel(const float* __restrict__ x,
                        const float* __restrict__ ke) {
    extern __shared__ char smem[];
    const uint32_t sb = smem_u32(smem);
    const int tid = threadIdx.x, lane = tid & 31, wid = tid >> 5;
    const int h = blockIdx.y, ntb = blockIdx.x;

    float* e2s = (float*)(smem + OFF_E2);      // [2][128]

    const __half* Bg = g_Bh + (size_t)h * C_ * DK_;
    const float* e2h = g_e2 + h * C_;

    // Prologue: B tile 0 (128 codes, 1024 chunks) + e2 tile 0
#pragma unroll 8
    for (int m = tid; m < TCB * 8; m += 128)
        cpa16(sb + OFF_B + (m >> 3) * SA + (m & 7) * 16, Bg + m * 8);
    if (tid < 32) cpa16(sb + OFF_E2 + tid * 16, e2h + tid * 4);
    cpa_commit();

    // A tile converted in-kernel to fp16
    {
        const float* xb = x + (size_t)(ntb * TM) * DIM_ + h * DK_;
#pragma unroll 8
        for (int m = tid; m < TM * 32; m += 128) {
            int r = m >> 5, dp = m & 31;
            float2 v = *(const float2*)(xb + (size_t)r * DIM_ + dp * 2);
            __half2 hv = __floats2half2_rn(v.x, v.y);
            *(__half2*)(smem + OFF_A + r * SA + dp * 4) = hv;
        }
    }

    // ldmatrix bases
    const uint32_t aAddr = sb + OFF_A +
        (uint32_t)((wid * 32 + (lane & 15)) * SA + (lane >> 4) * 16);
    const uint32_t bAddrBase =
        (uint32_t)(((lane & 7) + ((lane >> 4) & 1) * 8) * SA +
                   ((lane >> 3) & 1) * 16);

    float m1[4], m2[4], m3[4]; int i1[4], i2[4];
#pragma unroll
    for (int q = 0; q < 4; q++) {
        m1[q] = CUDART_INF_F; m2[q] = CUDART_INF_F; m3[q] = CUDART_INF_F;
        i1[q] = 0; i2[q] = 0;
    }

    for (int ct = 0; ct < NCT; ct++) {
        cpa_wait0();
        __syncthreads();

        if (ct + 1 < NCT) {
            const __half* Bt = Bg + (size_t)(ct + 1) * TCB * DK_;
            uint32_t dstb = sb + OFF_B + ((ct + 1) & 1) * B_TILE_BYTES;
#pragma unroll 8
            for (int m = tid; m < TCB * 8; m += 128)
                cpa16(dstb + (m >> 3) * SA + (m & 7) * 16, Bt + m * 8);
            if (tid < 32)
                cpa16(sb + OFF_E2 + ((ct + 1) & 1) * 512 + tid * 16,
                      e2h + (ct + 1) * TCB + tid * 4);
            cpa_commit();
        }

        // two 64-code subtiles per barrier span
#pragma unroll
        for (int sub = 0; sub < 2; sub++) {
            float acc[2][8][4];
#pragma unroll
            for (int mt = 0; mt < 2; mt++)
#pragma unroll
                for (int nt = 0; nt < 8; nt++)
#pragma unroll
                    for (int v = 0; v < 4; v++) acc[mt][nt][v] = 0.f;

            const uint32_t bAddr = sb + OFF_B + (ct & 1) * B_TILE_BYTES +
                                   (uint32_t)(sub * 64 * SA) + bAddrBase;

#pragma unroll
            for (int ks = 0; ks < 4; ks++) {
                uint32_t a[2][4], b[4][4];
#pragma unroll
                for (int mt = 0; mt < 2; mt++)
                    ldsm4(a[mt], aAddr + mt * (16 * SA) + ks * 32);
#pragma unroll
                for (int np = 0; np < 4; np++)
                    ldsm4(b[np], bAddr + np * (16 * SA) + ks * 32);
#pragma unroll
                for (int mt = 0; mt < 2; mt++)
#pragma unroll
                    for (int nt = 0; nt < 8; nt++)
                        mma16816(acc[mt][nt], a[mt], &b[nt >> 1][(nt & 1) * 2]);
            }

            // round-11 epilogue: paired fminf fast path vs m3, immediate ins3
            const float* e2c = e2s + (ct & 1) * 128 + sub * 64 + (lane & 3) * 2;
            const int cth = ct * TCB + sub * 64 + (lane & 3) * 2;
#pragma unroll
            for (int nt = 0; nt < 8; nt++) {
                float e20 = e2c[nt * 8], e21 = e2c[nt * 8 + 1];
#pragma unroll
                for (int mt = 0; mt < 2; mt++) {
#pragma unroll
                    for (int vp = 0; vp < 2; vp++) {
                        float s0 = fmaf(-2.f, acc[mt][nt][vp * 2],     e20);
                        float s1 = fmaf(-2.f, acc[mt][nt][vp * 2 + 1], e21);
                        int q = mt * 2 + vp;
                        if (fminf(s0, s1) < m3[q]) {    // rare after warmup
                            int c = cth + nt * 8;
                            ins3(s0, c,     m1[q], i1[q], m2[q], i2[q], m3[q]);
                            ins3(s1, c + 1, m1[q], i1[q], m2[q], i2[q], m3[q]);
                        }
                    }
                }
            }
        }
    }

    // quad reduce (lanes xor 1,2 cover disjoint columns, same rows)
#pragma unroll
    for (int q = 0; q < 4; q++) {
#pragma unroll
        for (int d = 1; d <= 2; d <<= 1) {
            float bm1 = __shfl_xor_sync(0xffffffffu, m1[q], d);
            int   bi1 = __shfl_xor_sync(0xffffffffu, i1[q], d);
            float bm2 = __shfl_xor_sync(0xffffffffu, m2[q], d);
            int   bi2 = __shfl_xor_sync(0xffffffffu, i2[q], d);
            float bm3 = __shfl_xor_sync(0xffffffffu, m3[q], d);
            merge3(m1[q], i1[q], m2[q], i2[q], m3[q], bm1, bi1, bm2, bi2, bm3);
        }
    }

    // finalize: each warp owns its rows (no cross-warp merge)
    if ((lane & 3) == 0) {
#pragma unroll
        for (int q = 0; q < 4; q++) {
            int r = wid * 32 + (q >> 1) * 16 + (q & 1) * 8 + (lane >> 2);
            int n   = ntb * TM + r;
            int row = h * N_ + n;
            g_idx[row] = i1[q];
            if (!(m2[q] - m1[q] > W_SEL)) {
                if (m3[q] - m1[q] > W_SEL) {
                    // winner provably in {i1, i2}: exact reference-order compare
                    int c1 = i1[q], c2 = i2[q];
                    const float* xp  = x  + (size_t)n * DIM_ + h * DK_;
                    const float* kp1 = ke + ((size_t)h * C_ + c1) * DK_;
                    const float* kp2 = ke + ((size_t)h * C_ + c2) * DK_;
                    float x2 = 0.f, d1 = 0.f, d2 = 0.f;
#pragma unroll
                    for (int d = 0; d < DK_; d++) {
                        float xv = __ldg(xp + d);
                        x2 = __fmaf_rn(xv, xv, x2);
                        d1 = __fmaf_rn(xv, __ldg(kp1 + d), d1);
                        d2 = __fmaf_rn(xv, __ldg(kp2 + d), d2);
                    }
                    float s1 = __fadd_rn(__fmaf_rn(-2.f, d1, x2), e2h[c1]);
                    float s2 = __fadd_rn(__fmaf_rn(-2.f, d2, x2), e2h[c2]);
                    g_idx[row] = (s2 < s1 || (s2 == s1 && c2 < c1)) ? c2 : c1;
                } else {
                    int p = atomicAdd(&g_cntB, 1);
                    g_listB[p] = row;
                }
            }
        }
    }
}

// ---------------------------------------------------------------------------
// Full replay (rare rows): exact fp32, smem-staged coalesced
// ---------------------------------------------------------------------------
__global__ void replay_kernel(const float* __restrict__ x,
                              const float* __restrict__ ke) {
    __shared__ float kt[128 * 65];
    __shared__ float xsr[DK_];
    __shared__ float rv[128];
    __shared__ int   ri[128];
    const int tid = threadIdx.x;
    for (int e = blockIdx.x; e < g_cntB; e += gridDim.x) {
        int row = g_listB[e];
        int h = row >> 12, n = row & (N_ - 1);
        if (tid < DK_) xsr[tid] = x[(size_t)n * DIM_ + h * DK_ + tid];
        __syncthreads();
        float x2 = 0.f;
#pragma unroll
        for (int d = 0; d < DK_; d++) x2 = __fmaf_rn(xsr[d], xsr[d], x2);
        const float* keh = ke + (size_t)h * C_ * DK_;
        const float* e2h = g_e2 + h * C_;
        float bv = CUDART_INF_F; int bi = 0;
        for (int tile = 0; tile < C_ / 128; tile++) {
            const float* kb = keh + (size_t)tile * 128 * DK_;
#pragma unroll 4
            for (int m = tid; m < 128 * 16; m += 128) {
                int r = m >> 4, c4 = m & 15;
                float4 v = *(const float4*)(kb + (size_t)r * DK_ + c4 * 4);
                kt[r * 65 + c4 * 4 + 0] = v.x;
                kt[r * 65 + c4 * 4 + 1] = v.y;
                kt[r * 65 + c4 * 4 + 2] = v.z;
                kt[r * 65 + c4 * 4 + 3] = v.w;
            }
            __syncthreads();
            float dot = 0.f;
#pragma unroll
            for (int d = 0; d < DK_; d++) dot = __fmaf_rn(xsr[d], kt[tid * 65 + d], dot);
            float s = __fadd_rn(__fmaf_rn(-2.f, dot, x2), e2h[tile * 128 + tid]);
            int c = tile * 128 + tid;
            if (s < bv) { bv = s; bi = c; }
            __syncthreads();
        }
        rv[tid] = bv; ri[tid] = bi;
        __syncthreads();
        if (tid == 0) {
            float b = rv[0]; int bix = ri[0];
            for (int t = 1; t < 128; t++) {
                float v = rv[t]; int c = ri[t];
                if (v < b || (v == b && c < bix)) { b = v; bix = c; }
            }
            g_idx[row] = bix;
        }
        __syncthreads();
    }
}

// ---------------------------------------------------------------------------
// Gather
// ---------------------------------------------------------------------------
__global__ void gather_kernel(const float* __restrict__ vals,
                              float* __restrict__ out) {
    int lin = blockIdx.x * blockDim.x + threadIdx.x;
    if (lin >= H_ * N_ * 16) return;
    int v4 = lin & 15; int hn = lin >> 4;
    int n = hn & (N_ - 1); int h = hn >> 12;
    int c = g_idx[hn];
    float4 v = *(const float4*)(vals + ((size_t)h * C_ + c) * DV_ + v4 * 4);
    *(float4*)(out + (size_t)n * DIM_ + h * DV_ + v4 * 4) = v;
}

// ---------------------------------------------------------------------------
extern "C" void kernel_launch(void* const* d_in, const int* in_sizes, int n_in,
                              void* d_out, int out_size) {
    const float* x    = (const float*)d_in[0];
    const float* ke   = (const float*)d_in[2];
    const float* vals = (const float*)d_in[3];
    float* out = (float*)d_out;

    cudaFuncSetAttribute(hmma_argmin_kernel,
                         cudaFuncAttributeMaxDynamicSharedMemorySize, SMEM_SZ);

    prep_be2_kernel<<<H_ * C_ / 64, 256>>>(ke);

    dim3 grid(N_ / TM, H_);
    hmma_argmin_kernel<<<grid, 128, SMEM_SZ>>>(x, ke);

    replay_kernel<<<148, 128>>>(x, ke);
    gather_kernel<<<(H_ * N_ * 16) / 256, 256>>>(vals, out);
}

// round 14
// speedup vs baseline: 1.6926x; 1.6926x over previous
#include <cuda_runtime.h>
#include <cuda_fp16.h>
#include <math_constants.h>
#include <stdint.h>

// Problem dims
#define B_   4
#define T_   1024
#define H_   12
#define C_   4096
#define DK_  64
#define DV_  64
#define N_   (B_*T_)      // 4096
#define DIM_ (H_*DK_)     // 768

// GEMM config: single-phase fp16 (K=64), certification window handles error.
#define TM   128          // rows per CTA
#define TCC  64           // codes per iteration
#define NCT  (C_/TCC)     // 64
#define SA   144          // smem row stride bytes (128 data + 16 pad)
#define B_TILE_BYTES (TCC*SA)     // 9216
#define W_SEL 5e-4f       // ambiguity window (~20 sigma of fp16-GEMM error)

// smem offsets
#define OFF_A   0                 // 128 * 144 = 18432
#define OFF_B   18432             // 2 buffers of 9216
#define OFF_E2  36864             // float e2s[2][64]
#define SMEM_SZ 37376

// Device scratch
__device__ __align__(1024) __half g_Bh[(size_t)H_*C_*DK_];
__device__ float g_e2[H_*C_];
__device__ int   g_idx[H_*N_];
__device__ int   g_listB[H_*N_];
__device__ int   g_cntB;

// ---------------- helpers ----------------
__device__ __forceinline__ uint32_t smem_u32(const void* p) {
    uint32_t a;
    asm("{ .reg .u64 t; cvta.to.shared.u64 t, %1; cvt.u32.u64 %0, t; }" : "=r"(a) : "l"(p));
    return a;
}
__device__ __forceinline__ void cpa16(uint32_t dst, const void* src) {
    asm volatile("cp.async.cg.shared.global [%0], [%1], 16;" :: "r"(dst), "l"(src));
}
__device__ __forceinline__ void cpa_commit() { asm volatile("cp.async.commit_group;" ::: "memory"); }
__device__ __forceinline__ void cpa_wait0()  { asm volatile("cp.async.wait_group 0;" ::: "memory"); }

__device__ __forceinline__ void ldsm4(uint32_t* r, uint32_t addr) {
    asm volatile("ldmatrix.sync.aligned.m8n8.x4.shared.b16 {%0,%1,%2,%3}, [%4];"
                 : "=r"(r[0]), "=r"(r[1]), "=r"(r[2]), "=r"(r[3]) : "r"(addr));
}
__device__ __forceinline__ void mma16816(float* d, const uint32_t* a, const uint32_t* b) {
    asm volatile("mma.sync.aligned.m16n8k16.row.col.f32.f16.f16.f32 "
                 "{%0,%1,%2,%3}, {%4,%5,%6,%7}, {%8,%9}, {%0,%1,%2,%3};"
                 : "+f"(d[0]), "+f"(d[1]), "+f"(d[2]), "+f"(d[3])
                 : "r"(a[0]), "r"(a[1]), "r"(a[2]), "r"(a[3]), "r"(b[0]), "r"(b[1]));
}

__device__ __forceinline__ void merge3(float& m1, int& i1, float& m2, int& i2, float& m3,
                                       float bm1, int bi1, float bm2, int bi2, float bm3) {
    if (bm1 < m1 || (bm1 == m1 && bi1 < i1)) {
        float t; int ti;
        t = m1; m1 = bm1; bm1 = t;  ti = i1; i1 = bi1; bi1 = ti;
        t = m2; m2 = bm2; bm2 = t;  ti = i2; i2 = bi2; bi2 = ti;
        t = m3; m3 = bm3; bm3 = t;
    }
    if (bm1 < m2 || (bm1 == m2 && bi1 < i2)) {
        m3 = fminf(m2, bm2);
        m2 = bm1; i2 = bi1;
    } else {
        m3 = fminf(m3, bm1);
    }
}

__device__ __forceinline__ void ins3(float s, int c, float& m1, int& i1,
                                     float& m2, int& i2, float& m3) {
    if (s < m1)      { m3 = m2; m2 = m1; i2 = i1; m1 = s; i1 = c; }
    else if (s < m2) { m3 = m2; m2 = s; i2 = c; }
    else if (s < m3) { m3 = s; }
}

// ---------------------------------------------------------------------------
// Fused prep: e2 (exact sequential order) + B fp16 convert
// ---------------------------------------------------------------------------
__global__ void prep_be2_kernel(const float* __restrict__ ke) {
    __shared__ float kt[64 * 65];
    const int tid = threadIdx.x;
    const int row0 = blockIdx.x * 64;
    if (blockIdx.x == 0 && tid == 0) g_cntB = 0;

#pragma unroll 4
    for (int m = tid; m < 64 * 16; m += 256) {
        int r = m >> 4, c4 = m & 15;
        float4 v = *(const float4*)(ke + (size_t)(row0 + r) * DK_ + c4 * 4);
        kt[r * 65 + c4 * 4 + 0] = v.x;
        kt[r * 65 + c4 * 4 + 1] = v.y;
        kt[r * 65 + c4 * 4 + 2] = v.z;
        kt[r * 65 + c4 * 4 + 3] = v.w;
    }
    __syncthreads();

    if (tid < 64) {
        float s = 0.f;
#pragma unroll
        for (int d = 0; d < DK_; d++) {
            float v = kt[tid * 65 + d];
            s = __fmaf_rn(v, v, s);
        }
        g_e2[row0 + tid] = s;
    }

#pragma unroll 4
    for (int m = tid; m < 64 * 32; m += 256) {
        int r = m >> 5, dp = m & 31;
        __half2 hv = __floats2half2_rn(kt[r * 65 + dp * 2], kt[r * 65 + dp * 2 + 1]);
        *(__half2*)(g_Bh + (size_t)(row0 + r) * DK_ + dp * 2) = hv;
    }
}

// ---------------------------------------------------------------------------
// Main: fp16 HMMA GEMM (K=64) + top-3 argmin; persistent A fragments
// grid = (32, 12); block = 128 (4 warps, each 32 rows x 64 cols)
// ---------------------------------------------------------------------------
__global__ __launch_bounds__(128, 3)
void hmma_argmin_kernel(const float* __restrict__ x,
                        const float* __restrict__ ke) {
    extern __shared__ char smem[];
    const uint32_t sb = smem_u32(smem);
    const int tid = threadIdx.x, lane = tid & 31, wid = tid >> 5;
    const int h = blockIdx.y, ntb = blockIdx.x;

    float* e2s = (float*)(smem + OFF_E2);      // [2][64]

    const __half* Bg = g_Bh + (size_t)h * C_ * DK_;
    const float* e2h = g_e2 + h * C_;

    // Prologue: B tile 0 (512 chunks) + e2 tile 0
#pragma unroll 4
    for (int m = tid; m < TCC * 8; m += 128)
        cpa16(sb + OFF_B + (m >> 3) * SA + (m & 7) * 16, Bg + m * 8);
    if (tid < 16) cpa16(sb + OFF_E2 + tid * 16, e2h + tid * 4);
    cpa_commit();

    // A tile converted in-kernel to fp16: 128 rows x 128 B
    {
        const float* xb = x + (size_t)(ntb * TM) * DIM_ + h * DK_;
#pragma unroll 8
        for (int m = tid; m < TM * 32; m += 128) {
            int r = m >> 5, dp = m & 31;
            float2 v = *(const float2*)(xb + (size_t)r * DIM_ + dp * 2);
            __half2 hv = __floats2half2_rn(v.x, v.y);
            *(__half2*)(smem + OFF_A + r * SA + dp * 4) = hv;
        }
    }
    __syncthreads();   // A tile visible

    // ldmatrix bases
    const uint32_t aAddr = sb + OFF_A +
        (uint32_t)((wid * 32 + (lane & 15)) * SA + (lane >> 4) * 16);
    const uint32_t bAddrBase =
        (uint32_t)(((lane & 7) + ((lane >> 4) & 1) * 8) * SA +
                   ((lane >> 3) & 1) * 16);

    // Persistent A fragments: identical across all 64 ct iterations
    uint32_t afr[4][2][4];
#pragma unroll
    for (int ks = 0; ks < 4; ks++)
#pragma unroll
        for (int mt = 0; mt < 2; mt++)
            ldsm4(afr[ks][mt], aAddr + mt * (16 * SA) + ks * 32);

    float m1[4], m2[4], m3[4]; int i1[4], i2[4];
#pragma unroll
    for (int q = 0; q < 4; q++) {
        m1[q] = CUDART_INF_F; m2[q] = CUDART_INF_F; m3[q] = CUDART_INF_F;
        i1[q] = 0; i2[q] = 0;
    }

    for (int ct = 0; ct < NCT; ct++) {
        cpa_wait0();          // tile ct resident
        __syncthreads();

        // prefetch tile ct+1 into the other buffer
        if (ct + 1 < NCT) {
            const __half* Bt = Bg + (size_t)(ct + 1) * TCC * DK_;
            uint32_t dstb = sb + OFF_B + ((ct + 1) & 1) * B_TILE_BYTES;
#pragma unroll 4
            for (int m = tid; m < TCC * 8; m += 128)
                cpa16(dstb + (m >> 3) * SA + (m & 7) * 16, Bt + m * 8);
            if (tid < 16)
                cpa16(sb + OFF_E2 + ((ct + 1) & 1) * 256 + tid * 16,
                      e2h + (ct + 1) * TCC + tid * 4);
            cpa_commit();
        }

        float acc[2][8][4];
#pragma unroll
        for (int mt = 0; mt < 2; mt++)
#pragma unroll
            for (int nt = 0; nt < 8; nt++)
#pragma unroll
                for (int v = 0; v < 4; v++) acc[mt][nt][v] = 0.f;

        const uint32_t bAddr = sb + OFF_B + (ct & 1) * B_TILE_BYTES + bAddrBase;

#pragma unroll
        for (int ks = 0; ks < 4; ks++) {
            uint32_t b[4][4];
#pragma unroll
            for (int np = 0; np < 4; np++)
                ldsm4(b[np], bAddr + np * (16 * SA) + ks * 32);
#pragma unroll
            for (int mt = 0; mt < 2; mt++)
#pragma unroll
                for (int nt = 0; nt < 8; nt++)
                    mma16816(acc[mt][nt], afr[ks][mt], &b[nt >> 1][(nt & 1) * 2]);
        }

        // epilogue: s = e2 - 2*dot; paired fminf fast path vs m3
        const float* e2c = e2s + (ct & 1) * 64 + (lane & 3) * 2;
        const int cth = ct * TCC + (lane & 3) * 2;
#pragma unroll
        for (int nt = 0; nt < 8; nt++) {
            float e20 = e2c[nt * 8], e21 = e2c[nt * 8 + 1];
#pragma unroll
            for (int mt = 0; mt < 2; mt++) {
#pragma unroll
                for (int vp = 0; vp < 2; vp++) {
                    float s0 = fmaf(-2.f, acc[mt][nt][vp * 2],     e20);
                    float s1 = fmaf(-2.f, acc[mt][nt][vp * 2 + 1], e21);
                    int q = mt * 2 + vp;
                    if (fminf(s0, s1) < m3[q]) {        // rare after warmup
                        int c = cth + nt * 8;
                        ins3(s0, c,     m1[q], i1[q], m2[q], i2[q], m3[q]);
                        ins3(s1, c + 1, m1[q], i1[q], m2[q], i2[q], m3[q]);
                    }
                }
            }
        }
    }

    // quad reduce (lanes xor 1,2 cover disjoint columns, same rows)
#pragma unroll
    for (int q = 0; q < 4; q++) {
#pragma unroll
        for (int d = 1; d <= 2; d <<= 1) {
            float bm1 = __shfl_xor_sync(0xffffffffu, m1[q], d);
            int   bi1 = __shfl_xor_sync(0xffffffffu, i1[q], d);
            float bm2 = __shfl_xor_sync(0xffffffffu, m2[q], d);
            int   bi2 = __shfl_xor_sync(0xffffffffu, i2[q], d);
            float bm3 = __shfl_xor_sync(0xffffffffu, m3[q], d);
            merge3(m1[q], i1[q], m2[q], i2[q], m3[q], bm1, bi1, bm2, bi2, bm3);
        }
    }

    // finalize: each warp owns its rows (no cross-warp merge)
    if ((lane & 3) == 0) {
#pragma unroll
        for (int q = 0; q < 4; q++) {
            int r = wid * 32 + (q >> 1) * 16 + (q & 1) * 8 + (lane >> 2);
            int n   = ntb * TM + r;
            int row = h * N_ + n;
            g_idx[row] = i1[q];
            if (!(m2[q] - m1[q] > W_SEL)) {
                if (m3[q] - m1[q] > W_SEL) {
                    // winner provably in {i1, i2}: exact reference-order compare
                    int c1 = i1[q], c2 = i2[q];
                    const float* xp  = x  + (size_t)n * DIM_ + h * DK_;
                    const float* kp1 = ke + ((size_t)h * C_ + c1) * DK_;
                    const float* kp2 = ke + ((size_t)h * C_ + c2) * DK_;
                    float x2 = 0.f, d1 = 0.f, d2 = 0.f;
#pragma unroll
                    for (int d = 0; d < DK_; d++) {
                        float xv = __ldg(xp + d);
                        x2 = __fmaf_rn(xv, xv, x2);
                        d1 = __fmaf_rn(xv, __ldg(kp1 + d), d1);
                        d2 = __fmaf_rn(xv, __ldg(kp2 + d), d2);
                    }
                    float s1 = __fadd_rn(__fmaf_rn(-2.f, d1, x2), e2h[c1]);
                    float s2 = __fadd_rn(__fmaf_rn(-2.f, d2, x2), e2h[c2]);
                    g_idx[row] = (s2 < s1 || (s2 == s1 && c2 < c1)) ? c2 : c1;
                } else {
                    int p = atomicAdd(&g_cntB, 1);
                    g_listB[p] = row;
                }
            }
        }
    }
}

// ---------------------------------------------------------------------------
// Full replay (rare rows): exact fp32, smem-staged coalesced
// ---------------------------------------------------------------------------
__global__ void replay_kernel(const float* __restrict__ x,
                              const float* __restrict__ ke) {
    __shared__ float kt[128 * 65];
    __shared__ float xsr[DK_];
    __shared__ float rv[128];
    __shared__ int   ri[128];
    const int tid = threadIdx.x;
    for (int e = blockIdx.x; e < g_cntB; e += gridDim.x) {
        int row = g_listB[e];
        int h = row >> 12, n = row & (N_ - 1);
        if (tid < DK_) xsr[tid] = x[(size_t)n * DIM_ + h * DK_ + tid];
        __syncthreads();
        float x2 = 0.f;
#pragma unroll
        for (int d = 0; d < DK_; d++) x2 = __fmaf_rn(xsr[d], xsr[d], x2);
        const float* keh = ke + (size_t)h * C_ * DK_;
        const float* e2h = g_e2 + h * C_;
        float bv = CUDART_INF_F; int bi = 0;
        for (int tile = 0; tile < C_ / 128; tile++) {
            const float* kb = keh + (size_t)tile * 128 * DK_;
#pragma unroll 4
            for (int m = tid; m < 128 * 16; m += 128) {
                int r = m >> 4, c4 = m & 15;
                float4 v = *(const float4*)(kb + (size_t)r * DK_ + c4 * 4);
                kt[r * 65 + c4 * 4 + 0] = v.x;
                kt[r * 65 + c4 * 4 + 1] = v.y;
                kt[r * 65 + c4 * 4 + 2] = v.z;
                kt[r * 65 + c4 * 4 + 3] = v.w;
            }
            __syncthreads();
            float dot = 0.f;
#pragma unroll
            for (int d = 0; d < DK_; d++) dot = __fmaf_rn(xsr[d], kt[tid * 65 + d], dot);
            float s = __fadd_rn(__fmaf_rn(-2.f, dot, x2), e2h[tile * 128 + tid]);
            int c = tile * 128 + tid;
            if (s < bv) { bv = s; bi = c; }
            __syncthreads();
        }
        rv[tid] = bv; ri[tid] = bi;
        __syncthreads();
        if (tid == 0) {
            float b = rv[0]; int bix = ri[0];
            for (int t = 1; t < 128; t++) {
                float v = rv[t]; int c = ri[t];
                if (v < b || (v == b && c < bix)) { b = v; bix = c; }
            }
            g_idx[row] = bix;
        }
        __syncthreads();
    }
}

// ---------------------------------------------------------------------------
// Gather
// ---------------------------------------------------------------------------
__global__ void gather_kernel(const float* __restrict__ vals,
                              float* __restrict__ out) {
    int lin = blockIdx.x * blockDim.x + threadIdx.x;
    if (lin >= H_ * N_ * 16) return;
    int v4 = lin & 15; int hn = lin >> 4;
    int n = hn & (N_ - 1); int h = hn >> 12;
    int c = g_idx[hn];
    float4 v = *(const float4*)(vals + ((size_t)h * C_ + c) * DV_ + v4 * 4);
    *(float4*)(out + (size_t)n * DIM_ + h * DV_ + v4 * 4) = v;
}

// ---------------------------------------------------------------------------
extern "C" void kernel_launch(void* const* d_in, const int* in_sizes, int n_in,
                              void* d_out, int out_size) {
    const float* x    = (const float*)d_in[0];
    const float* ke   = (const float*)d_in[2];
    const float* vals = (const float*)d_in[3];
    float* out = (float*)d_out;

    cudaFuncSetAttribute(hmma_argmin_kernel,
                         cudaFuncAttributeMaxDynamicSharedMemorySize, SMEM_SZ);

    prep_be2_kernel<<<H_ * C_ / 64, 256>>>(ke);

    dim3 grid(N_ / TM, H_);
    hmma_argmin_kernel<<<grid, 128, SMEM_SZ>>>(x, ke);

    replay_kernel<<<148, 128>>>(x, ke);
    gather_kernel<<<(H_ * N_ * 16) / 256, 256>>>(vals, out);
}